// round 1
// baseline (speedup 1.0000x reference)
#include <cuda_runtime.h>
#include <cuda_bf16.h>

// k-winners-take-all over channels: x (rows=200704, C=256) fp32.
// Keep x >= (26th largest in row), else 0.  Warp-per-row, exact radix select.

constexpr int CHANNELS = 256;
constexpr int KSEL     = 26;   // max(1, round(0.1 * 256))

// Order-preserving float->uint key (total order, ascending).
__device__ __forceinline__ unsigned f2k(float f) {
    unsigned u = __float_as_uint(f);
    return u ^ ((unsigned)((int)u >> 31) | 0x80000000u);
}

// compare-exchange: a <- max, b <- min  (descending sort)
__device__ __forceinline__ void ce(unsigned &a, unsigned &b) {
    unsigned hi = a > b ? a : b;
    unsigned lo = a > b ? b : a;
    a = hi; b = lo;
}

__global__ void __launch_bounds__(256)
kwta_kernel(const float* __restrict__ x, float* __restrict__ y, int rows) {
    int gw = (blockIdx.x * blockDim.x + threadIdx.x) >> 5;   // global warp = row
    if (gw >= rows) return;
    int lane = threadIdx.x & 31;

    const float4* xp = reinterpret_cast<const float4*>(x) + (size_t)gw * (CHANNELS / 4);
    float4 a = __ldcs(xp + lane);        // elems [lane*4, lane*4+4)
    float4 b = __ldcs(xp + 32 + lane);   // elems [128 + lane*4, ...)

    unsigned s0 = f2k(a.x), s1 = f2k(a.y), s2 = f2k(a.z), s3 = f2k(a.w);
    unsigned s4 = f2k(b.x), s5 = f2k(b.y), s6 = f2k(b.z), s7 = f2k(b.w);

    // Batcher odd-even mergesort for 8, descending (19 CE = 38 IMNMX)
    ce(s0,s1); ce(s2,s3); ce(s4,s5); ce(s6,s7);
    ce(s0,s2); ce(s1,s3); ce(s4,s6); ce(s5,s7);
    ce(s1,s2); ce(s5,s6);
    ce(s0,s4); ce(s1,s5); ce(s2,s6); ce(s3,s7);
    ce(s2,s4); ce(s3,s5);
    ce(s1,s2); ce(s3,s4); ce(s5,s6);
    // now s0 >= s1 >= ... >= s7

    // MSB-first radix select: largest T with |{key >= T}| >= KSEL
    unsigned prefix = 0;
    #pragma unroll
    for (int bit = 31; bit >= 0; --bit) {
        unsigned cand = prefix | (1u << bit);
        // branchless binary search: cnt = #{s_i >= cand} in [0,8]
        bool c1 = (s3 >= cand);               // cnt >= 4 ?
        unsigned t1 = c1 ? s5 : s1;
        bool c2 = (t1 >= cand);               // +2 ?
        unsigned tA = c2 ? s2 : s0;
        unsigned tB = c2 ? s6 : s4;
        unsigned t2 = c1 ? tB : tA;
        bool c3 = (t2 >= cand);               // +1 ?
        bool c0 = (s7 >= cand);               // all-8 correction
        unsigned cnt = (c1 ? 4u : 0u) + (c2 ? 2u : 0u)
                     + (c3 ? 1u : 0u) + (c0 ? 1u : 0u);
        unsigned tot = __reduce_add_sync(0xFFFFFFFFu, cnt);   // REDUX.SUM
        if (tot >= (unsigned)KSEL) prefix = cand;             // SEL
    }

    // prefix is the exact key of the 26th-largest element; unmap to float
    unsigned tu = (prefix & 0x80000000u) ? (prefix ^ 0x80000000u) : ~prefix;
    float thr = __uint_as_float(tu);

    float4 oa, ob;
    oa.x = (a.x >= thr) ? a.x : 0.0f;
    oa.y = (a.y >= thr) ? a.y : 0.0f;
    oa.z = (a.z >= thr) ? a.z : 0.0f;
    oa.w = (a.w >= thr) ? a.w : 0.0f;
    ob.x = (b.x >= thr) ? b.x : 0.0f;
    ob.y = (b.y >= thr) ? b.y : 0.0f;
    ob.z = (b.z >= thr) ? b.z : 0.0f;
    ob.w = (b.w >= thr) ? b.w : 0.0f;

    float4* yp = reinterpret_cast<float4*>(y) + (size_t)gw * (CHANNELS / 4);
    __stcs(yp + lane, oa);
    __stcs(yp + 32 + lane, ob);
}

extern "C" void kernel_launch(void* const* d_in, const int* in_sizes, int n_in,
                              void* d_out, int out_size) {
    const float* x = (const float*)d_in[0];
    float* y = (float*)d_out;
    int rows = in_sizes[0] / CHANNELS;            // 200704
    int total_threads = rows * 32;                // one warp per row
    int block = 256;
    int grid = (total_threads + block - 1) / block;
    kwta_kernel<<<grid, block>>>(x, y, rows);
}

// round 2
// speedup vs baseline: 1.2008x; 1.2008x over previous
#include <cuda_runtime.h>
#include <cuda_bf16.h>

// k-winners-take-all over channels: x (rows=200704, C=256) fp32.
// Keep x >= (26th largest in row), else 0.
// Warp-per-row, exact MSB radix select with data-driven early exit.

constexpr int CHANNELS = 256;
constexpr unsigned KSEL = 26;   // max(1, round(0.1 * 256))

// Order-preserving float->uint key (ascending). 2 inst: SHF.R.S32 + LOP3.
__device__ __forceinline__ unsigned f2k(float f) {
    unsigned u = __float_as_uint(f);
    unsigned m = (unsigned)((int)u >> 31);
    return u ^ (m | 0x80000000u);        // single LOP3: a ^ (b | c)
}

// compare-exchange: a <- max, b <- min  (descending sort)
__device__ __forceinline__ void ce(unsigned &a, unsigned &b) {
    unsigned hi = a > b ? a : b;
    unsigned lo = a > b ? b : a;
    a = hi; b = lo;
}

__global__ void __launch_bounds__(256)
kwta_kernel(const float* __restrict__ x, float* __restrict__ y, int rows) {
    int gw = (blockIdx.x * blockDim.x + threadIdx.x) >> 5;   // global warp = row
    if (gw >= rows) return;
    int lane = threadIdx.x & 31;

    const float4* xp = reinterpret_cast<const float4*>(x) + (size_t)gw * (CHANNELS / 4);
    float4 a = __ldcs(xp + lane);
    float4 b = __ldcs(xp + 32 + lane);

    unsigned s0 = f2k(a.x), s1 = f2k(a.y), s2 = f2k(a.z), s3 = f2k(a.w);
    unsigned s4 = f2k(b.x), s5 = f2k(b.y), s6 = f2k(b.z), s7 = f2k(b.w);

    // Batcher odd-even mergesort for 8, descending (19 CE)
    ce(s0,s1); ce(s2,s3); ce(s4,s5); ce(s6,s7);
    ce(s0,s2); ce(s1,s3); ce(s4,s6); ce(s5,s7);
    ce(s1,s2); ce(s5,s6);
    ce(s0,s4); ce(s1,s5); ce(s2,s6); ce(s3,s7);
    ce(s2,s4); ce(s3,s5);
    ce(s1,s2); ce(s3,s4); ce(s5,s6);
    // s0 >= s1 >= ... >= s7

    // MSB radix select for the KSEL-th largest key, with early exit when the
    // bracket [prefix, U) isolates a single element.
    unsigned prefix = 0u;            // cnt_ge(prefix) >= KSEL always
    unsigned U      = 0xFFFFFFFFu;   // cnt_ge(U) < KSEL (0xFFFFFFFF = NaN key, absent)
    unsigned cntP   = 256u;          // cnt_ge(prefix)
    unsigned cntU   = 0u;            // cnt_ge(U)
    unsigned thrkey;

    #pragma unroll 1
    for (int bit = 31; ; --bit) {
        unsigned cand = prefix | (1u << bit);
        // per-lane cnt = #{s_i >= cand}, branchless binary search on sorted regs
        bool c1 = (s3 >= cand);
        unsigned t1 = c1 ? s5 : s1;
        bool c2 = (t1 >= cand);
        unsigned tA = c2 ? s2 : s0;
        unsigned tB = c2 ? s6 : s4;
        unsigned t2 = c1 ? tB : tA;
        bool c3 = (t2 >= cand);
        bool c0 = (s7 >= cand);
        unsigned cnt = 4u * (unsigned)c1 + 2u * (unsigned)c2
                     + (unsigned)c3 + (unsigned)c0;
        unsigned tot = __reduce_add_sync(0xFFFFFFFFu, cnt);
        if (tot >= KSEL) { prefix = cand; cntP = tot; }
        else             { U = cand;      cntU = tot; }

        if (cntP - cntU == 1u) {
            // exactly one key in [prefix, U): it is the KSEL-th largest.
            // per-lane: largest s_j with s_j < U (sorted desc -> first such)
            unsigned t = s7;
            t = (s6 < U) ? s6 : t;
            t = (s5 < U) ? s5 : t;
            t = (s4 < U) ? s4 : t;
            t = (s3 < U) ? s3 : t;
            t = (s2 < U) ? s2 : t;
            t = (s1 < U) ? s1 : t;
            t = (s0 < U) ? s0 : t;
            unsigned m = (t >= prefix && t < U) ? t : 0u;
            thrkey = __reduce_max_sync(0xFFFFFFFFu, m);
            break;
        }
        if (bit == 0) { thrkey = prefix; break; }
    }

    // unmap key -> float threshold
    unsigned tu = (thrkey & 0x80000000u) ? (thrkey ^ 0x80000000u) : ~thrkey;
    float thr = __uint_as_float(tu);

    float4 oa, ob;
    oa.x = (a.x >= thr) ? a.x : 0.0f;
    oa.y = (a.y >= thr) ? a.y : 0.0f;
    oa.z = (a.z >= thr) ? a.z : 0.0f;
    oa.w = (a.w >= thr) ? a.w : 0.0f;
    ob.x = (b.x >= thr) ? b.x : 0.0f;
    ob.y = (b.y >= thr) ? b.y : 0.0f;
    ob.z = (b.z >= thr) ? b.z : 0.0f;
    ob.w = (b.w >= thr) ? b.w : 0.0f;

    float4* yp = reinterpret_cast<float4*>(y) + (size_t)gw * (CHANNELS / 4);
    __stcs(yp + lane, oa);
    __stcs(yp + 32 + lane, ob);
}

extern "C" void kernel_launch(void* const* d_in, const int* in_sizes, int n_in,
                              void* d_out, int out_size) {
    const float* x = (const float*)d_in[0];
    float* y = (float*)d_out;
    int rows = in_sizes[0] / CHANNELS;            // 200704
    int total_threads = rows * 32;                // one warp per row
    int block = 256;
    int grid = (total_threads + block - 1) / block;
    kwta_kernel<<<grid, block>>>(x, y, rows);
}